// round 1
// baseline (speedup 1.0000x reference)
#include <cuda_runtime.h>

// UnfoldMatmulFold fused gather kernel.
//
// Derivation: out[b,y,x,c] = sum over patches (h,kh),(w,kw) with 2h+kh=y+1,
// 2w+kw=x+1 of  mm[b,h,w,kh,kw,c],  where
// mm[...,c=n*64+d] = sum_q attn[b,h,w,n,3kh+kw,q] * vv[b,2h+qh-1,2w+qw-1,c]
// (q = 3qh+qw, vv zero-padded).
//
// Even y has exactly one contributing h (=y/2, kh=1); odd y has two
// (h=(y-1)/2 kh=2, h=(y+1)/2 kh=0). Therefore a 2x2 output quad
// (y0=2qy, x0=2qx) depends only on patches h in {qy,qy+1}, w in {qx,qx+1}
// and the 5x5 vv neighborhood rows y0-1..y0+3, cols x0-1..x0+3.
//
// Block = one (b, quad). Threads split the 768 channels (8 per thread).
// attn for the 4 patches (all 12 heads) is staged in shared memory.

namespace {

constexpr int Bc  = 64;
constexpr int Hc  = 28;
constexpr int Wc  = 28;
constexpr int Cch = 768;
constexpr int NH  = 12;
constexpr int GH  = 14;          // 14x14 quad grid
constexpr int CV  = 8;           // channels per thread
constexpr int TPB = Cch / CV;    // 96 threads
constexpr int SEG = NH * 81;     // 972 floats of attn per (b,h,w)

// Row-part tables (index r = vv neighborhood row 0..4).
// Each rowpart: which patch row (0=h0,1=h1), qh, kh, and which quad pixel py.
//   r in {0,1,2}: patch h0, qh=r, contributes kh=1 -> py0 and kh=2 -> py1
//   r in {2,3,4}: patch h1, qh=r-2, contributes kh=0 -> py1
__device__ constexpr int RPN[5]    = {2,2,3,1,1};
__device__ constexpr int RPR[5][3] = {{0,0,0},{0,0,0},{0,0,1},{1,0,0},{1,0,0}};
__device__ constexpr int RQH[5][3] = {{0,0,0},{1,1,0},{2,2,0},{1,0,0},{2,0,0}};
__device__ constexpr int RKH[5][3] = {{1,2,0},{1,2,0},{1,2,0},{0,0,0},{0,0,0}};
__device__ constexpr int RPY[5][3] = {{0,1,0},{0,1,0},{0,1,1},{1,0,0},{1,0,0}};

__global__ __launch_bounds__(TPB)
void fused_ufmf_kernel(const float* __restrict__ vv,
                       const float* __restrict__ attn,
                       float* __restrict__ out)
{
    const int t  = threadIdx.x;           // 0..95, channel group
    const int qy = blockIdx.x / GH;
    const int qx = blockIdx.x % GH;
    const int b  = blockIdx.y;

    const int y0 = 2 * qy;
    const int x0 = 2 * qx;
    const int c0 = t * CV;
    const int n  = c0 >> 6;               // head index (CV=8 divides 64)

    const bool h1ok = (qy < GH - 1);
    const bool w1ok = (qx < GH - 1);

    __shared__ float s_attn[4][SEG];      // patches: 0:(h0,w0) 1:(h0,w1) 2:(h1,w0) 3:(h1,w1)

    // Cooperative attn staging (invalid patches alias patch 0; never read).
    {
        const int base00 = ((b * GH + qy) * GH + qx) * SEG;
        const float* g0 = attn + base00;
        const float* g1 = attn + base00 + (w1ok ? SEG : 0);
        const float* g2 = attn + base00 + (h1ok ? GH * SEG : 0);
        const float* g3 = attn + base00 + ((h1ok && w1ok) ? (GH + 1) * SEG : 0);
        for (int i = t; i < SEG; i += TPB) {
            s_attn[0][i] = g0[i];
            s_attn[1][i] = g1[i];
            s_attn[2][i] = g2[i];
            s_attn[3][i] = g3[i];
        }
    }
    __syncthreads();

    float acc[2][2][CV];
#pragma unroll
    for (int i = 0; i < 2; ++i)
#pragma unroll
        for (int j = 0; j < 2; ++j)
#pragma unroll
            for (int k = 0; k < CV; ++k) acc[i][j][k] = 0.0f;

    const float* sa    = &s_attn[0][0] + n * 81;       // + patch*SEG + p*9 + q
    const float* vbase = vv + (b * Hc * Wc) * Cch + c0;

#pragma unroll
    for (int r = 0; r < 5; ++r) {
        const int gy = y0 - 1 + r;
        const bool rok = (unsigned)gy < (unsigned)Hc;
#pragma unroll
        for (int s = 0; s < 5; ++s) {
            const int gx = x0 - 1 + s;
            if (!(rok && ((unsigned)gx < (unsigned)Wc))) continue;  // zero-pad region

            const float* vp = vbase + (gy * Wc + gx) * Cch;
            const float4 va = *reinterpret_cast<const float4*>(vp);
            const float4 vb = *reinterpret_cast<const float4*>(vp + 4);
            const float v[CV] = {va.x, va.y, va.z, va.w, vb.x, vb.y, vb.z, vb.w};

#pragma unroll
            for (int i = 0; i < RPN[r]; ++i) {
                if (RPR[r][i] == 1 && !h1ok) continue;
#pragma unroll
                for (int j = 0; j < RPN[s]; ++j) {
                    if (RPR[s][j] == 1 && !w1ok) continue;
                    const int patch = RPR[r][i] * 2 + RPR[s][j];
                    const int p     = RKH[r][i] * 3 + RKH[s][j];
                    const int q     = RQH[r][i] * 3 + RQH[s][j];
                    const float w   = sa[patch * SEG + p * 9 + q];
#pragma unroll
                    for (int k = 0; k < CV; ++k)
                        acc[RPY[r][i]][RPY[s][j]][k] += w * v[k];
                }
            }
        }
    }

    // Each quad pixel is produced exactly once -> plain coalesced stores.
#pragma unroll
    for (int i = 0; i < 2; ++i)
#pragma unroll
        for (int j = 0; j < 2; ++j) {
            float* o = out + ((b * Hc + (y0 + i)) * Wc + (x0 + j)) * Cch + c0;
            float4 o0 = make_float4(acc[i][j][0], acc[i][j][1], acc[i][j][2], acc[i][j][3]);
            float4 o1 = make_float4(acc[i][j][4], acc[i][j][5], acc[i][j][6], acc[i][j][7]);
            *reinterpret_cast<float4*>(o)     = o0;
            *reinterpret_cast<float4*>(o + 4) = o1;
        }
}

} // namespace

extern "C" void kernel_launch(void* const* d_in, const int* in_sizes, int n_in,
                              void* d_out, int out_size)
{
    const float* vv   = (const float*)d_in[0];
    const float* attn = (const float*)d_in[1];
    float* out        = (float*)d_out;

    dim3 grid(GH * GH, Bc);   // 196 quads x 64 batch
    fused_ufmf_kernel<<<grid, TPB>>>(vv, attn, out);
}

// round 3
// speedup vs baseline: 1.1063x; 1.1063x over previous
#include <cuda_runtime.h>

// UnfoldMatmulFold, fused gather, QX=2 tile.
//
// out[b,y,x,c] = sum over (h,kh),(w,kw) with 2h+kh=y+1, 2w+kw=x+1 of
//   sum_q attn[b,h,w,n,p=(kh,kw),q=(qh,qw)] * vv[b,2h+qh-1,2w+qw-1,c]
//
// Block = (b, qy, tqx): output rows y0..y0+1 (y0=2qy), cols x0..x0+3 (x0=4tqx).
// Needs patches h in {qy,qy+1} (ph 0..1), w in {2tqx..2tqx+2} (pw 0..2),
// vv rows y0-1..y0+3 (r 0..4), cols x0-1..x0+5 (s 0..6, s = 2pw+qw).
//
// attn staged to smem transposed/padded: [patch][n][p][qh][4] so a qw-triple
// is one aligned LDS.128. Invalid patches staged as zeros.

namespace {

constexpr int Hc  = 28;
constexpr int Wc  = 28;
constexpr int Cch = 768;
constexpr int NH  = 12;
constexpr int GH  = 14;
constexpr int CV  = 8;
constexpr int TPB = 96;
constexpr int SEG = NH * 81;            // 972 floats per (b,h,w)
constexpr int PATCH_W  = 9 * 3 * 4;     // 108: per-head padded weights
constexpr int PATCH_SZ = NH * PATCH_W;  // 1296

// Row tables: per vv row r, entries (ph, qh, kh, oy)
__device__ constexpr int RN [5]    = {2,2,3,1,1};
__device__ constexpr int RPH[5][3] = {{0,0,0},{0,0,0},{0,0,1},{1,0,0},{1,0,0}};
__device__ constexpr int RQH[5][3] = {{0,0,0},{1,1,0},{2,2,0},{1,0,0},{2,0,0}};
__device__ constexpr int RKH[5][3] = {{1,2,0},{1,2,0},{1,2,0},{0,0,0},{0,0,0}};
__device__ constexpr int ROY[5][3] = {{0,1,0},{0,1,0},{0,1,1},{1,0,0},{1,0,0}};

// Col tables: per patch-col pw, entries (kw, ox)
__device__ constexpr int CN [3]    = {2,3,1};
__device__ constexpr int CKW[3][3] = {{1,2,0},{0,1,2},{0,0,0}};
__device__ constexpr int COX[3][3] = {{0,1,0},{1,2,3},{3,0,0}};

__global__ __launch_bounds__(TPB)
void fused_ufmf_kernel(const float* __restrict__ vv,
                       const float* __restrict__ attn,
                       float* __restrict__ out)
{
    const int t   = threadIdx.x;           // 0..95
    const int qy  = blockIdx.x / 7;        // 0..13
    const int tqx = blockIdx.x % 7;        // 0..6
    const int b   = blockIdx.y;

    const int y0 = 2 * qy;
    const int x0 = 4 * tqx;
    const int c0 = t * CV;
    const int n  = t >> 3;                 // head

    __shared__ __align__(16) float s_w[6 * PATCH_SZ];   // 31104 B

    // ---- Stage attn (transposed+padded); zero-fill invalid patches ----
#pragma unroll
    for (int patch = 0; patch < 6; ++patch) {
        const int ph = patch / 3, pw = patch % 3;
        const int h = qy + ph, w = 2 * tqx + pw;
        const bool val = (h < GH) && (w < GH);
        const int hs = val ? h : 0, ws = val ? w : 0;
        const float* g = attn + ((size_t)((b * GH + hs) * GH + ws)) * SEG;
        float* sp = s_w + patch * PATCH_SZ;
        for (int i = t; i < SEG; i += TPB) {
            float x = 0.0f;
            if (val) x = __ldg(g + i);
            const int nn  = i / 81;
            const int rem = i - nn * 81;
            const int p   = rem / 9;
            const int q   = rem - p * 9;
            sp[nn * PATCH_W + p * 12 + q + q / 3] = x;   // dst = n*108 + p*12 + qh*4 + qw
        }
    }
    __syncthreads();

    float acc[2][4][CV];
#pragma unroll
    for (int i = 0; i < 2; ++i)
#pragma unroll
        for (int j = 0; j < 4; ++j)
#pragma unroll
            for (int k = 0; k < CV; ++k) acc[i][j][k] = 0.0f;

    const float* vbase = vv + (size_t)b * Hc * Wc * Cch + c0;
    const float* swn   = s_w + n * PATCH_W;

#pragma unroll
    for (int r = 0; r < 5; ++r) {
        const int gy = y0 - 1 + r;
        if ((unsigned)gy >= (unsigned)Hc) continue;     // zero-padded rows

        float v[7][CV];

#define LOADC(S)                                                             \
        do {                                                                 \
            const int gx = x0 - 1 + (S);                                     \
            if ((unsigned)gx < (unsigned)Wc) {                               \
                const float* vp = vbase + ((size_t)gy * Wc + gx) * Cch;      \
                const float4 a_ = *reinterpret_cast<const float4*>(vp);      \
                const float4 b_ = *reinterpret_cast<const float4*>(vp + 4);  \
                v[S][0]=a_.x; v[S][1]=a_.y; v[S][2]=a_.z; v[S][3]=a_.w;      \
                v[S][4]=b_.x; v[S][5]=b_.y; v[S][6]=b_.z; v[S][7]=b_.w;      \
            } else {                                                         \
                _Pragma("unroll")                                            \
                for (int k = 0; k < CV; ++k) v[S][k] = 0.0f;                 \
            }                                                                \
        } while (0)

#define DO_PW(PW)                                                            \
        _Pragma("unroll")                                                    \
        for (int e = 0; e < RN[r]; ++e) {                                    \
            const int ph = RPH[r][e], qh = RQH[r][e];                        \
            const int kh = RKH[r][e], oy = ROY[r][e];                        \
            _Pragma("unroll")                                                \
            for (int f = 0; f < CN[PW]; ++f) {                               \
                const int kw = CKW[PW][f], ox = COX[PW][f];                  \
                const float4 w4 = *reinterpret_cast<const float4*>(          \
                    swn + (ph * 3 + (PW)) * PATCH_SZ                         \
                        + (kh * 3 + kw) * 12 + qh * 4);                      \
                _Pragma("unroll")                                            \
                for (int k = 0; k < CV; ++k)                                 \
                    acc[oy][ox][k] += w4.x * v[2*(PW)  ][k]                  \
                                    + w4.y * v[2*(PW)+1][k]                  \
                                    + w4.z * v[2*(PW)+2][k];                 \
            }                                                                \
        }

        LOADC(0); LOADC(1); LOADC(2);
        DO_PW(0);
        LOADC(3); LOADC(4);
        DO_PW(1);
        LOADC(5); LOADC(6);
        DO_PW(2);

#undef LOADC
#undef DO_PW
    }

    // ---- Stores: each output element produced exactly once ----
#pragma unroll
    for (int oy = 0; oy < 2; ++oy)
#pragma unroll
        for (int ox = 0; ox < 4; ++ox) {
            float* o = out + ((size_t)((b * Hc + (y0 + oy)) * Wc + (x0 + ox))) * Cch + c0;
            *reinterpret_cast<float4*>(o) =
                make_float4(acc[oy][ox][0], acc[oy][ox][1], acc[oy][ox][2], acc[oy][ox][3]);
            *reinterpret_cast<float4*>(o + 4) =
                make_float4(acc[oy][ox][4], acc[oy][ox][5], acc[oy][ox][6], acc[oy][ox][7]);
        }
}

} // namespace

extern "C" void kernel_launch(void* const* d_in, const int* in_sizes, int n_in,
                              void* d_out, int out_size)
{
    const float* vv   = (const float*)d_in[0];
    const float* attn = (const float*)d_in[1];
    float* out        = (float*)d_out;

    dim3 grid(14 * 7, 64);   // (qy,tqx) tiles x batch
    fused_ufmf_kernel<<<grid, TPB>>>(vv, attn, out);
}

// round 4
// speedup vs baseline: 1.3449x; 1.2157x over previous
#include <cuda_runtime.h>

// UnfoldMatmulFold, fused gather, 2x4-px tile, CV=4 channels/thread,
// packed f32x2 FMA (sm_103a).
//
// out[b,y,x,c] = sum over (h,kh),(w,kw) with 2h+kh=y+1, 2w+kw=x+1 of
//   sum_q attn[b,h,w,n,p=(kh,kw),q=(qh,qw)] * vv[b,2h+qh-1,2w+qw-1,c]
//
// Block = (b, qy, tqx): output rows y0..y0+1, cols x0..x0+3.
// attn staged to smem [patch][n][p][qh][4] so a qw-triple is one LDS.128.

namespace {

constexpr int Hc  = 28;
constexpr int Wc  = 28;
constexpr int Cch = 768;
constexpr int NH  = 12;
constexpr int GH  = 14;
constexpr int CV  = 4;
constexpr int TPB = 192;                // Cch / CV
constexpr int SEG = NH * 81;            // 972 floats per (b,h,w)
constexpr int PATCH_W  = 9 * 3 * 4;     // 108 padded weights per head
constexpr int PATCH_SZ = NH * PATCH_W;  // 1296

// Row tables: per vv row r, entries (ph, qh, kh, oy)
__device__ constexpr int RN [5]    = {2,2,3,1,1};
__device__ constexpr int RPH[5][3] = {{0,0,0},{0,0,0},{0,0,1},{1,0,0},{1,0,0}};
__device__ constexpr int RQH[5][3] = {{0,0,0},{1,1,0},{2,2,0},{1,0,0},{2,0,0}};
__device__ constexpr int RKH[5][3] = {{1,2,0},{1,2,0},{1,2,0},{0,0,0},{0,0,0}};
__device__ constexpr int ROY[5][3] = {{0,1,0},{0,1,0},{0,1,1},{1,0,0},{1,0,0}};

// Col tables: per patch-col pw, entries (kw, ox)
__device__ constexpr int CN [3]    = {2,3,1};
__device__ constexpr int CKW[3][3] = {{1,2,0},{0,1,2},{0,0,0}};
__device__ constexpr int COX[3][3] = {{0,1,0},{1,2,3},{3,0,0}};

__device__ __forceinline__ void fma2(unsigned long long& d,
                                     unsigned long long a,
                                     unsigned long long b) {
    asm("fma.rn.f32x2 %0, %1, %2, %0;" : "+l"(d) : "l"(a), "l"(b));
}
__device__ __forceinline__ unsigned long long pack2(float w) {
    unsigned long long r;
    unsigned int wi = __float_as_uint(w);
    asm("mov.b64 %0, {%1, %1};" : "=l"(r) : "r"(wi));
    return r;
}

__global__ __launch_bounds__(TPB, 3)
void fused_ufmf_kernel(const float* __restrict__ vv,
                       const float* __restrict__ attn,
                       float* __restrict__ out)
{
    const int t   = threadIdx.x;            // 0..191
    const int qy  = blockIdx.x / 7;
    const int tqx = blockIdx.x % 7;
    const int b   = blockIdx.y;

    const int y0 = 2 * qy;
    const int x0 = 4 * tqx;
    const int c0 = t * CV;
    const int n  = t >> 4;                   // head (16 threads/head)

    __shared__ __align__(16) float s_w[6 * PATCH_SZ];   // 31104 B

    // ---- Stage attn (float4 loads, transposed/padded scatter stores) ----
#pragma unroll
    for (int patch = 0; patch < 6; ++patch) {
        const int ph = patch / 3, pw = patch % 3;
        const int h = qy + ph, w = 2 * tqx + pw;
        const bool val = (h < GH) && (w < GH);
        const int hs = val ? h : 0, ws = val ? w : 0;
        const float4* g4 = reinterpret_cast<const float4*>(
            attn + ((size_t)((b * GH + hs) * GH + ws)) * SEG);
        float* sp = s_w + patch * PATCH_SZ;
        for (int i4 = t; i4 < SEG / 4; i4 += TPB) {       // 243 float4s
            float4 x4 = make_float4(0.f, 0.f, 0.f, 0.f);
            if (val) x4 = __ldg(g4 + i4);
            const float xs[4] = {x4.x, x4.y, x4.z, x4.w};
#pragma unroll
            for (int j = 0; j < 4; ++j) {
                const int i   = 4 * i4 + j;
                const int nn  = i / 81;
                const int rem = i - nn * 81;
                const int p   = rem / 9;
                const int q   = rem - p * 9;
                sp[nn * PATCH_W + p * 12 + q + q / 3] = xs[j];
            }
        }
    }
    __syncthreads();

    unsigned long long acc[2][4][2];
#pragma unroll
    for (int i = 0; i < 2; ++i)
#pragma unroll
        for (int j = 0; j < 4; ++j) {
            acc[i][j][0] = 0ull; acc[i][j][1] = 0ull;
        }

    const float* vbase = vv + (size_t)b * Hc * Wc * Cch + c0;
    const float* swn   = s_w + n * PATCH_W;

#pragma unroll
    for (int r = 0; r < 5; ++r) {
        const int gy = y0 - 1 + r;
        if ((unsigned)gy >= (unsigned)Hc) continue;       // zero-padded rows

        unsigned long long v[7][2];

#define LOADC(S)                                                              \
        do {                                                                  \
            const int gx = x0 - 1 + (S);                                      \
            if ((unsigned)gx < (unsigned)Wc) {                                \
                const ulonglong2 u = *reinterpret_cast<const ulonglong2*>(    \
                    vbase + ((size_t)gy * Wc + gx) * Cch);                    \
                v[S][0] = u.x; v[S][1] = u.y;                                 \
            } else { v[S][0] = 0ull; v[S][1] = 0ull; }                        \
        } while (0)

#define DO_PW(PW)                                                             \
        _Pragma("unroll")                                                     \
        for (int e = 0; e < RN[r]; ++e) {                                     \
            const int ph = RPH[r][e], qh = RQH[r][e];                         \
            const int kh = RKH[r][e], oy = ROY[r][e];                         \
            _Pragma("unroll")                                                 \
            for (int f = 0; f < CN[PW]; ++f) {                                \
                const int kw = CKW[PW][f], ox = COX[PW][f];                   \
                const float4 w4 = *reinterpret_cast<const float4*>(           \
                    swn + (ph * 3 + (PW)) * PATCH_SZ                          \
                        + (kh * 3 + kw) * 12 + qh * 4);                       \
                const unsigned long long wx = pack2(w4.x);                    \
                const unsigned long long wy = pack2(w4.y);                    \
                const unsigned long long wz = pack2(w4.z);                    \
                _Pragma("unroll")                                             \
                for (int k = 0; k < 2; ++k) {                                 \
                    fma2(acc[oy][ox][k], wx, v[2*(PW)  ][k]);                 \
                    fma2(acc[oy][ox][k], wy, v[2*(PW)+1][k]);                 \
                    fma2(acc[oy][ox][k], wz, v[2*(PW)+2][k]);                 \
                }                                                             \
            }                                                                 \
        }

        LOADC(0); LOADC(1); LOADC(2);
        DO_PW(0);
        LOADC(3); LOADC(4);
        DO_PW(1);
        LOADC(5); LOADC(6);
        DO_PW(2);

#undef LOADC
#undef DO_PW
    }

    // ---- Stores: each output element produced exactly once ----
#pragma unroll
    for (int oy = 0; oy < 2; ++oy)
#pragma unroll
        for (int ox = 0; ox < 4; ++ox) {
            ulonglong2 o2;
            o2.x = acc[oy][ox][0];
            o2.y = acc[oy][ox][1];
            *reinterpret_cast<ulonglong2*>(
                out + ((size_t)((b * Hc + (y0 + oy)) * Wc + (x0 + ox))) * Cch + c0) = o2;
        }
}

} // namespace

extern "C" void kernel_launch(void* const* d_in, const int* in_sizes, int n_in,
                              void* d_out, int out_size)
{
    const float* vv   = (const float*)d_in[0];
    const float* attn = (const float*)d_in[1];
    float* out        = (float*)d_out;

    dim3 grid(14 * 7, 64);   // (qy,tqx) tiles x batch
    fused_ufmf_kernel<<<grid, TPB>>>(vv, attn, out);
}

// round 5
// speedup vs baseline: 1.4859x; 1.1048x over previous
#include <cuda_runtime.h>

// UnfoldMatmulFold, fused gather, 2x4-px tile, CV=4, f32x2 FMA,
// row-pipelined vv loads (double-buffered), hoisted staging indices.
//
// out[b,y,x,c] = sum over (h,kh),(w,kw) with 2h+kh=y+1, 2w+kw=x+1 of
//   sum_q attn[b,h,w,n,p=(kh,kw),q=(qh,qw)] * vv[b,2h+qh-1,2w+qw-1,c]
//
// Block = (b, qy, tqx): output rows y0..y0+1, cols x0..x0+3.
// attn staged to smem [patch][n][p][qh][4]: a qw-triple is one LDS.128.

namespace {

constexpr int Hc  = 28;
constexpr int Wc  = 28;
constexpr int Cch = 768;
constexpr int NH  = 12;
constexpr int GH  = 14;
constexpr int CV  = 4;
constexpr int TPB = 192;                // Cch / CV
constexpr int SEG = NH * 81;            // 972 floats per (b,h,w)
constexpr int SEG4 = SEG / 4;           // 243 float4s
constexpr int PATCH_W  = 9 * 3 * 4;     // 108 padded weights per head
constexpr int PATCH_SZ = NH * PATCH_W;  // 1296

// Row tables: per vv row r, entries (ph, qh, kh, oy)
__device__ constexpr int RN [5]    = {2,2,3,1,1};
__device__ constexpr int RPH[5][3] = {{0,0,0},{0,0,0},{0,0,1},{1,0,0},{1,0,0}};
__device__ constexpr int RQH[5][3] = {{0,0,0},{1,1,0},{2,2,0},{1,0,0},{2,0,0}};
__device__ constexpr int RKH[5][3] = {{1,2,0},{1,2,0},{1,2,0},{0,0,0},{0,0,0}};
__device__ constexpr int ROY[5][3] = {{0,1,0},{0,1,0},{0,1,1},{1,0,0},{1,0,0}};

// Col tables: per patch-col pw, entries (kw, ox)
__device__ constexpr int CN [3]    = {2,3,1};
__device__ constexpr int CKW[3][3] = {{1,2,0},{0,1,2},{0,0,0}};
__device__ constexpr int COX[3][3] = {{0,1,0},{1,2,3},{3,0,0}};

__device__ __forceinline__ void fma2(unsigned long long& d,
                                     unsigned long long a,
                                     unsigned long long b) {
    asm("fma.rn.f32x2 %0, %1, %2, %0;" : "+l"(d) : "l"(a), "l"(b));
}
__device__ __forceinline__ unsigned long long pack2(float w) {
    unsigned long long r;
    unsigned int wi = __float_as_uint(w);
    asm("mov.b64 %0, {%1, %1};" : "=l"(r) : "r"(wi));
    return r;
}

__device__ __forceinline__ void stage_dst(int i4, int* dst) {
#pragma unroll
    for (int j = 0; j < 4; ++j) {
        const int i   = 4 * i4 + j;
        const int nn  = i / 81;
        const int rem = i - nn * 81;
        const int p   = rem / 9;
        const int q   = rem - p * 9;
        dst[j] = nn * PATCH_W + p * 12 + q + q / 3;
    }
}

__global__ __launch_bounds__(TPB, 3)
void fused_ufmf_kernel(const float* __restrict__ vv,
                       const float* __restrict__ attn,
                       float* __restrict__ out)
{
    const int t   = threadIdx.x;            // 0..191
    const int qy  = blockIdx.x / 7;
    const int tqx = blockIdx.x % 7;
    const int b   = blockIdx.y;

    const int y0 = 2 * qy;
    const int x0 = 4 * tqx;
    const int c0 = t * CV;
    const int n  = t >> 4;                   // head (16 threads/head)

    __shared__ __align__(16) float s_w[6 * PATCH_SZ];   // 31104 B

    // ---- Stage attn: scatter indices hoisted out of the patch loop ----
    {
        int dst0[4], dst1[4];
        stage_dst(t, dst0);
        const bool has2 = (t + TPB < SEG4);               // t < 51
        if (has2) stage_dst(t + TPB, dst1);

#pragma unroll
        for (int patch = 0; patch < 6; ++patch) {
            const int ph = patch / 3, pw = patch % 3;
            const int h = qy + ph, w = 2 * tqx + pw;
            const bool val = (h < GH) && (w < GH);
            const int hs = val ? h : 0, ws = val ? w : 0;
            const float4* g4 = reinterpret_cast<const float4*>(
                attn + ((size_t)((b * GH + hs) * GH + ws)) * SEG);
            float* sp = s_w + patch * PATCH_SZ;

            float4 x4 = make_float4(0.f, 0.f, 0.f, 0.f);
            if (val) x4 = __ldg(g4 + t);
            sp[dst0[0]] = x4.x; sp[dst0[1]] = x4.y;
            sp[dst0[2]] = x4.z; sp[dst0[3]] = x4.w;
            if (has2) {
                float4 y4 = make_float4(0.f, 0.f, 0.f, 0.f);
                if (val) y4 = __ldg(g4 + t + TPB);
                sp[dst1[0]] = y4.x; sp[dst1[1]] = y4.y;
                sp[dst1[2]] = y4.z; sp[dst1[3]] = y4.w;
            }
        }
    }
    __syncthreads();

    unsigned long long acc[2][4][2];
#pragma unroll
    for (int i = 0; i < 2; ++i)
#pragma unroll
        for (int j = 0; j < 4; ++j) {
            acc[i][j][0] = 0ull; acc[i][j][1] = 0ull;
        }

    const float* vbase = vv + (size_t)b * Hc * Wc * Cch + c0;
    const float* swn   = s_w + n * PATCH_W;

    // Two row buffers (registers); OOB rows/cols are zero-filled so the
    // unrolled pipeline has no control flow.
    unsigned long long vbuf[2][7][2];

#define LOADROW(P, R)                                                         \
    do {                                                                      \
        const int gy_ = y0 - 1 + (R);                                         \
        const bool rok_ = (unsigned)gy_ < (unsigned)Hc;                       \
        _Pragma("unroll")                                                     \
        for (int s_ = 0; s_ < 7; ++s_) {                                      \
            const int gx_ = x0 - 1 + s_;                                      \
            if (rok_ && ((unsigned)gx_ < (unsigned)Wc)) {                     \
                const ulonglong2 u_ = *reinterpret_cast<const ulonglong2*>(   \
                    vbase + ((size_t)gy_ * Wc + gx_) * Cch);                  \
                vbuf[P][s_][0] = u_.x; vbuf[P][s_][1] = u_.y;                 \
            } else { vbuf[P][s_][0] = 0ull; vbuf[P][s_][1] = 0ull; }          \
        }                                                                     \
    } while (0)

#define COMPROW(P, R)                                                         \
    do {                                                                      \
        _Pragma("unroll")                                                     \
        for (int pw = 0; pw < 3; ++pw) {                                      \
            _Pragma("unroll")                                                 \
            for (int e = 0; e < RN[R]; ++e) {                                 \
                const int ph = RPH[R][e], qh = RQH[R][e];                     \
                const int kh = RKH[R][e], oy = ROY[R][e];                     \
                _Pragma("unroll")                                             \
                for (int f = 0; f < CN[pw]; ++f) {                            \
                    const int kw = CKW[pw][f], ox = COX[pw][f];               \
                    const float4 w4 = *reinterpret_cast<const float4*>(       \
                        swn + (ph * 3 + pw) * PATCH_SZ                        \
                            + (kh * 3 + kw) * 12 + qh * 4);                   \
                    const unsigned long long wx = pack2(w4.x);                \
                    const unsigned long long wy = pack2(w4.y);                \
                    const unsigned long long wz = pack2(w4.z);                \
                    _Pragma("unroll")                                         \
                    for (int k = 0; k < 2; ++k) {                             \
                        fma2(acc[oy][ox][k], wx, vbuf[P][2*pw  ][k]);         \
                        fma2(acc[oy][ox][k], wy, vbuf[P][2*pw+1][k]);         \
                        fma2(acc[oy][ox][k], wz, vbuf[P][2*pw+2][k]);         \
                    }                                                         \
                }                                                             \
            }                                                                 \
        }                                                                     \
    } while (0)

    LOADROW(0, 0);
    LOADROW(1, 1); COMPROW(0, 0);
    LOADROW(0, 2); COMPROW(1, 1);
    LOADROW(1, 3); COMPROW(0, 2);
    LOADROW(0, 4); COMPROW(1, 3);
    COMPROW(0, 4);

#undef LOADROW
#undef COMPROW

    // ---- Stores: each output element produced exactly once ----
#pragma unroll
    for (int oy = 0; oy < 2; ++oy)
#pragma unroll
        for (int ox = 0; ox < 4; ++ox) {
            ulonglong2 o2;
            o2.x = acc[oy][ox][0];
            o2.y = acc[oy][ox][1];
            *reinterpret_cast<ulonglong2*>(
                out + ((size_t)((b * Hc + (y0 + oy)) * Wc + (x0 + ox))) * Cch + c0) = o2;
        }
}

} // namespace

extern "C" void kernel_launch(void* const* d_in, const int* in_sizes, int n_in,
                              void* d_out, int out_size)
{
    const float* vv   = (const float*)d_in[0];
    const float* attn = (const float*)d_in[1];
    float* out        = (float*)d_out;

    dim3 grid(14 * 7, 64);   // (qy,tqx) tiles x batch
    fused_ufmf_kernel<<<grid, TPB>>>(vv, attn, out);
}

// round 6
// speedup vs baseline: 1.7695x; 1.1908x over previous
#include <cuda_runtime.h>

// UnfoldMatmulFold, fused gather. 2x4-px tile per block, CV=2 channels/thread,
// TPB=384 (one warp per head -> warp-uniform weight smem loads).
//
// out[b,y,x,c] = sum over (h,kh),(w,kw) with 2h+kh=y+1, 2w+kw=x+1 of
//   sum_q attn[b,h,w,n,p=(kh,kw),q=(qh,qw)] * vv[b,2h+qh-1,2w+qw-1,c]
//
// attn staged to smem [patch][n][p][qh][4]: a qw-triple is one LDS.128.

namespace {

constexpr int Hc  = 28;
constexpr int Wc  = 28;
constexpr int Cch = 768;
constexpr int NH  = 12;
constexpr int GH  = 14;
constexpr int TPB = 384;                // 12 warps = 12 heads
constexpr int SEG = NH * 81;            // 972 floats per (b,h,w)
constexpr int SEG4 = SEG / 4;           // 243 float4s
constexpr int PATCH_W  = 9 * 3 * 4;     // 108 padded weights per head
constexpr int PATCH_SZ = NH * PATCH_W;  // 1296

// Row tables: per vv row r, entries (ph, qh, kh, oy)
__device__ constexpr int RN [5]    = {2,2,3,1,1};
__device__ constexpr int RPH[5][3] = {{0,0,0},{0,0,0},{0,0,1},{1,0,0},{1,0,0}};
__device__ constexpr int RQH[5][3] = {{0,0,0},{1,1,0},{2,2,0},{1,0,0},{2,0,0}};
__device__ constexpr int RKH[5][3] = {{1,2,0},{1,2,0},{1,2,0},{0,0,0},{0,0,0}};
__device__ constexpr int ROY[5][3] = {{0,1,0},{0,1,0},{0,1,1},{1,0,0},{1,0,0}};

// Col tables: per patch-col pw, entries (kw, ox)
__device__ constexpr int CN [3]    = {2,3,1};
__device__ constexpr int CKW[3][3] = {{1,2,0},{0,1,2},{0,0,0}};
__device__ constexpr int COX[3][3] = {{0,1,0},{1,2,3},{3,0,0}};

__global__ __launch_bounds__(TPB, 3)
void fused_ufmf_kernel(const float* __restrict__ vv,
                       const float* __restrict__ attn,
                       float* __restrict__ out)
{
    const int t    = threadIdx.x;           // 0..383
    const int qy   = blockIdx.x / 7;
    const int tqx  = blockIdx.x % 7;
    const int b    = blockIdx.y;

    const int y0   = 2 * qy;
    const int x0   = 4 * tqx;
    const int n    = t >> 5;                // head == warp id
    const int lane = t & 31;
    const int c0   = n * 64 + lane * 2;     // 2 channels per thread

    __shared__ __align__(16) float s_w[6 * PATCH_SZ];   // 31104 B

    // ---- Stage attn (threads 0..242 active; scatter indices hoisted) ----
    if (t < SEG4) {
        int dst[4];
#pragma unroll
        for (int j = 0; j < 4; ++j) {
            const int i   = 4 * t + j;
            const int nn  = i / 81;
            const int rem = i - nn * 81;
            const int p   = rem / 9;
            const int q   = rem - p * 9;
            dst[j] = nn * PATCH_W + p * 12 + q + q / 3;
        }
#pragma unroll
        for (int patch = 0; patch < 6; ++patch) {
            const int ph = patch / 3, pw = patch % 3;
            const int h = qy + ph, w = 2 * tqx + pw;
            const bool val = (h < GH) && (w < GH);
            const int hs = val ? h : 0, ws = val ? w : 0;
            const float4* g4 = reinterpret_cast<const float4*>(
                attn + ((size_t)((b * GH + hs) * GH + ws)) * SEG);
            float4 x4 = make_float4(0.f, 0.f, 0.f, 0.f);
            if (val) x4 = __ldg(g4 + t);
            float* sp = s_w + patch * PATCH_SZ;
            sp[dst[0]] = x4.x; sp[dst[1]] = x4.y;
            sp[dst[2]] = x4.z; sp[dst[3]] = x4.w;
        }
    }
    __syncthreads();

    float2 acc[2][4];
#pragma unroll
    for (int i = 0; i < 2; ++i)
#pragma unroll
        for (int j = 0; j < 4; ++j) acc[i][j] = make_float2(0.f, 0.f);

    const float* vbase = vv + (size_t)b * Hc * Wc * Cch + c0;
    const float* swn   = s_w + n * PATCH_W;

#pragma unroll
    for (int r = 0; r < 5; ++r) {
        const int gy = y0 - 1 + r;
        const bool rok = (unsigned)gy < (unsigned)Hc;

        float2 v[7];
#pragma unroll
        for (int s = 0; s < 7; ++s) {
            const int gx = x0 - 1 + s;
            if (rok && ((unsigned)gx < (unsigned)Wc))
                v[s] = *reinterpret_cast<const float2*>(
                    vbase + ((size_t)gy * Wc + gx) * Cch);
            else
                v[s] = make_float2(0.f, 0.f);
        }

#pragma unroll
        for (int pw = 0; pw < 3; ++pw) {
#pragma unroll
            for (int e = 0; e < RN[r]; ++e) {
                const int ph = RPH[r][e], qh = RQH[r][e];
                const int kh = RKH[r][e], oy = ROY[r][e];
#pragma unroll
                for (int f = 0; f < CN[pw]; ++f) {
                    const int kw = CKW[pw][f], ox = COX[pw][f];
                    const float4 w4 = *reinterpret_cast<const float4*>(
                        swn + (ph * 3 + pw) * PATCH_SZ
                            + (kh * 3 + kw) * 12 + qh * 4);
                    float2& a = acc[oy][ox];
                    a.x += w4.x * v[2*pw  ].x;  a.y += w4.x * v[2*pw  ].y;
                    a.x += w4.y * v[2*pw+1].x;  a.y += w4.y * v[2*pw+1].y;
                    a.x += w4.z * v[2*pw+2].x;  a.y += w4.z * v[2*pw+2].y;
                }
            }
        }
    }

    // ---- Stores: each output element produced exactly once ----
#pragma unroll
    for (int oy = 0; oy < 2; ++oy)
#pragma unroll
        for (int ox = 0; ox < 4; ++ox) {
            *reinterpret_cast<float2*>(
                out + ((size_t)((b * Hc + (y0 + oy)) * Wc + (x0 + ox))) * Cch + c0)
                = acc[oy][ox];
        }
}

} // namespace

extern "C" void kernel_launch(void* const* d_in, const int* in_sizes, int n_in,
                              void* d_out, int out_size)
{
    const float* vv   = (const float*)d_in[0];
    const float* attn = (const float*)d_in[1];
    float* out        = (float*)d_out;

    dim3 grid(14 * 7, 64);   // (qy,tqx) tiles x batch
    fused_ufmf_kernel<<<grid, TPB>>>(vv, attn, out);
}

// round 7
// speedup vs baseline: 1.7707x; 1.0007x over previous
#include <cuda_runtime.h>

// UnfoldMatmulFold, fused gather. 4x4-px tile per block, CV=2 channels/thread,
// TPB=384 (one warp per head -> warp-uniform weight smem loads).
//
// out[b,y,x,c] = sum over (h,kh),(w,kw) with 2h+kh=y+1, 2w+kw=x+1 of
//   sum_q attn[b,h,w,n,p=(kh,kw),q=(qh,qw)] * vv[b,2h+qh-1,2w+qw-1,c]
//
// Block = (b, ty, tx): output rows 4ty..4ty+3, cols 4tx..4tx+3.
// Patches h in {2ty..2ty+2} (ph 0..2), w in {2tx..2tx+2} (pw 0..2).
// vv rows y0-1..y0+5 (r 0..6), cols x0-1..x0+5 (s 0..6).
// attn staged to smem [patch][n][p][qh][4]: a qw-triple is one LDS.128.

namespace {

constexpr int Hc  = 28;
constexpr int Wc  = 28;
constexpr int Cch = 768;
constexpr int NH  = 12;
constexpr int GH  = 14;
constexpr int TPB = 384;                // 12 warps = 12 heads
constexpr int SEG = NH * 81;            // 972 floats per (b,h,w)
constexpr int SEG4 = SEG / 4;           // 243 float4s
constexpr int PATCH_W  = 9 * 3 * 4;     // 108 padded weights per head
constexpr int PATCH_SZ = NH * PATCH_W;  // 1296

// Row tables for R=4: per vv row r (0..6), entries (ph, qh, kh, oy).
//   ph=0: oy=kh-1 (kh 1,2); ph=1: oy=kh+1 (kh 0..2); ph=2: oy=kh+3 (kh 0).
//   constraint 2*ph + qh = r.
__device__ constexpr int RN [7]    = {2,2,5,3,4,1,1};
__device__ constexpr int RPH[7][5] = {{0,0,0,0,0},{0,0,0,0,0},{0,0,1,1,1},
                                      {1,1,1,0,0},{1,1,1,2,0},{2,0,0,0,0},{2,0,0,0,0}};
__device__ constexpr int RQH[7][5] = {{0,0,0,0,0},{1,1,0,0,0},{2,2,0,0,0},
                                      {1,1,1,0,0},{2,2,2,0,0},{1,0,0,0,0},{2,0,0,0,0}};
__device__ constexpr int RKH[7][5] = {{1,2,0,0,0},{1,2,0,0,0},{1,2,0,1,2},
                                      {0,1,2,0,0},{0,1,2,0,0},{0,0,0,0,0},{0,0,0,0,0}};
__device__ constexpr int ROY[7][5] = {{0,1,0,0,0},{0,1,0,0,0},{0,1,1,2,3},
                                      {1,2,3,0,0},{1,2,3,3,0},{3,0,0,0,0},{3,0,0,0,0}};

// Col tables (C=4): per patch-col pw, entries (kw, ox)
__device__ constexpr int CN [3]    = {2,3,1};
__device__ constexpr int CKW[3][3] = {{1,2,0},{0,1,2},{0,0,0}};
__device__ constexpr int COX[3][3] = {{0,1,0},{1,2,3},{3,0,0}};

__global__ __launch_bounds__(TPB, 2)
void fused_ufmf_kernel(const float* __restrict__ vv,
                       const float* __restrict__ attn,
                       float* __restrict__ out)
{
    const int t    = threadIdx.x;           // 0..383
    const int ty   = blockIdx.x / 7;
    const int tx   = blockIdx.x % 7;
    const int b    = blockIdx.y;

    const int y0   = 4 * ty;
    const int x0   = 4 * tx;
    const int n    = t >> 5;                // head == warp id
    const int lane = t & 31;
    const int c0   = n * 64 + lane * 2;     // 2 channels per thread

    __shared__ __align__(16) float s_w[9 * PATCH_SZ];   // 46656 B

    // ---- Stage attn for 9 patches (threads 0..242; indices hoisted) ----
    if (t < SEG4) {
        int dst[4];
#pragma unroll
        for (int j = 0; j < 4; ++j) {
            const int i   = 4 * t + j;
            const int nn  = i / 81;
            const int rem = i - nn * 81;
            const int p   = rem / 9;
            const int q   = rem - p * 9;
            dst[j] = nn * PATCH_W + p * 12 + q + q / 3;
        }
#pragma unroll
        for (int patch = 0; patch < 9; ++patch) {
            const int ph = patch / 3, pw = patch % 3;
            const int h = 2 * ty + ph, w = 2 * tx + pw;
            const bool val = (h < GH) && (w < GH);
            const int hs = val ? h : 0, ws = val ? w : 0;
            const float4* g4 = reinterpret_cast<const float4*>(
                attn + ((size_t)((b * GH + hs) * GH + ws)) * SEG);
            float4 x4 = make_float4(0.f, 0.f, 0.f, 0.f);
            if (val) x4 = __ldg(g4 + t);
            float* sp = s_w + patch * PATCH_SZ;
            sp[dst[0]] = x4.x; sp[dst[1]] = x4.y;
            sp[dst[2]] = x4.z; sp[dst[3]] = x4.w;
        }
    }
    __syncthreads();

    float2 acc[4][4];
#pragma unroll
    for (int i = 0; i < 4; ++i)
#pragma unroll
        for (int j = 0; j < 4; ++j) acc[i][j] = make_float2(0.f, 0.f);

    const float* vbase = vv + (size_t)b * Hc * Wc * Cch + c0;
    const float* swn   = s_w + n * PATCH_W;

#pragma unroll
    for (int r = 0; r < 7; ++r) {
        const int gy = y0 - 1 + r;
        const bool rok = (unsigned)gy < (unsigned)Hc;

        float2 v[7];
#pragma unroll
        for (int s = 0; s < 7; ++s) {
            const int gx = x0 - 1 + s;
            if (rok && ((unsigned)gx < (unsigned)Wc))
                v[s] = *reinterpret_cast<const float2*>(
                    vbase + ((size_t)gy * Wc + gx) * Cch);
            else
                v[s] = make_float2(0.f, 0.f);
        }

#pragma unroll
        for (int e = 0; e < RN[r]; ++e) {
            const int ph = RPH[r][e], qh = RQH[r][e];
            const int kh = RKH[r][e], oy = ROY[r][e];
#pragma unroll
            for (int pw = 0; pw < 3; ++pw) {
#pragma unroll
                for (int f = 0; f < CN[pw]; ++f) {
                    const int kw = CKW[pw][f], ox = COX[pw][f];
                    const float4 w4 = *reinterpret_cast<const float4*>(
                        swn + (ph * 3 + pw) * PATCH_SZ
                            + (kh * 3 + kw) * 12 + qh * 4);
                    float2& a = acc[oy][ox];
                    a.x += w4.x * v[2*pw  ].x;  a.y += w4.x * v[2*pw  ].y;
                    a.x += w4.y * v[2*pw+1].x;  a.y += w4.y * v[2*pw+1].y;
                    a.x += w4.z * v[2*pw+2].x;  a.y += w4.z * v[2*pw+2].y;
                }
            }
        }
    }

    // ---- Stores: each output element produced exactly once ----
#pragma unroll
    for (int oy = 0; oy < 4; ++oy)
#pragma unroll
        for (int ox = 0; ox < 4; ++ox) {
            *reinterpret_cast<float2*>(
                out + ((size_t)((b * Hc + (y0 + oy)) * Wc + (x0 + ox))) * Cch + c0)
                = acc[oy][ox];
        }
}

} // namespace

extern "C" void kernel_launch(void* const* d_in, const int* in_sizes, int n_in,
                              void* d_out, int out_size)
{
    const float* vv   = (const float*)d_in[0];
    const float* attn = (const float*)d_in[1];
    float* out        = (float*)d_out;

    dim3 grid(7 * 7, 64);   // (ty,tx) 4x4 tiles x batch
    fused_ufmf_kernel<<<grid, TPB>>>(vv, attn, out);
}